// round 3
// baseline (speedup 1.0000x reference)
#include <cuda_runtime.h>
#include <math.h>

// Problem dims
#define BSZ 4
#define HDIM 96
#define WDIM 96
#define CDIM 128
#define HW (HDIM*WDIM)
#define NT (BSZ*HW)          // 36864 tokens
#define NBH 9
#define RPD 8
#define HID 128
#define PRE_N 640            // [Ad | Bd | Ar | Br | V] each 128 wide

// Scratch (no allocation allowed -> __device__ globals)
__device__ float g_norm[(size_t)NT*CDIM];
__device__ float g_pre[(size_t)NT*PRE_N];
__device__ float g_msg[(size_t)NT*CDIM];
__device__ float g_Wc[(size_t)CDIM*PRE_N];   // combined weights [k][n]
__device__ float g_rpb[2*NBH*HID];           // rel-pos + bias table, d then r

__device__ __forceinline__ float sp_f(float x) {
    // jax.nn.softplus = logaddexp(x, 0)
    return fmaxf(x, 0.f) + log1pf(expf(-fabsf(x)));
}
__device__ __forceinline__ float gelu_f(float x) {
    return 0.5f * x * (1.f + erff(x * 0.70710678118654752f));
}

// ---------------------------------------------------------------------------
// Weight prep: Wc[k][n] for n-blocks {Ad, Bd, Ar, Br, V}
// Ad = W1a + W1c ; Bd = W1b - W1c (same for r); V = v_w
// ---------------------------------------------------------------------------
__global__ void k_prep_w(const float* __restrict__ dw1,
                         const float* __restrict__ rw1,
                         const float* __restrict__ vw) {
    int i = blockIdx.x * blockDim.x + threadIdx.x;
    if (i >= CDIM * PRE_N) return;
    int k = i / PRE_N, n = i % PRE_N;
    float v;
    if (n < 128)        v = dw1[k*HID + n]         + dw1[(256+k)*HID + n];
    else if (n < 256)   v = dw1[(128+k)*HID + (n-128)] - dw1[(256+k)*HID + (n-128)];
    else if (n < 384)   v = rw1[k*HID + (n-256)]       + rw1[(256+k)*HID + (n-256)];
    else if (n < 512)   v = rw1[(128+k)*HID + (n-384)] - rw1[(256+k)*HID + (n-384)];
    else                v = vw[k*CDIM + (n-512)];
    g_Wc[i] = v;
}

// rpb[m][nb][j] = b1[j] + sum_p rel_pos[nb][p] * w1[384+p][j]
__global__ void k_prep_rpb(const float* __restrict__ relp,
                           const float* __restrict__ dw1, const float* __restrict__ db1,
                           const float* __restrict__ rw1, const float* __restrict__ rb1) {
    int i = blockIdx.x * blockDim.x + threadIdx.x;
    if (i >= 2 * NBH * HID) return;
    int m = i / (NBH*HID);
    int nb = (i / HID) % NBH;
    int j = i % HID;
    const float* w1 = m ? rw1 : dw1;
    const float* b1 = m ? rb1 : db1;
    float acc = b1[j];
#pragma unroll
    for (int p = 0; p < RPD; p++)
        acc += relp[nb*RPD + p] * w1[(384+p)*HID + j];
    g_rpb[i] = acc;
}

// ---------------------------------------------------------------------------
// LayerNorm 1: one warp per token row of 128
// ---------------------------------------------------------------------------
__global__ void k_ln1(const float* __restrict__ tokens,
                      const float* __restrict__ w, const float* __restrict__ b) {
    int warp = threadIdx.x >> 5, lane = threadIdx.x & 31;
    int row = blockIdx.x * 8 + warp;
    const float4 x = ((const float4*)(tokens + (size_t)row*CDIM))[lane];
    float s = x.x + x.y + x.z + x.w;
#pragma unroll
    for (int o = 16; o; o >>= 1) s += __shfl_xor_sync(0xffffffffu, s, o);
    float m = s * (1.f/128.f);
    float d0 = x.x - m, d1 = x.y - m, d2 = x.z - m, d3 = x.w - m;
    float v = d0*d0 + d1*d1 + d2*d2 + d3*d3;
#pragma unroll
    for (int o = 16; o; o >>= 1) v += __shfl_xor_sync(0xffffffffu, v, o);
    float r = rsqrtf(v * (1.f/128.f) + 1e-5f);
    const float4 wv = ((const float4*)w)[lane];
    const float4 bv = ((const float4*)b)[lane];
    float4 o4;
    o4.x = d0*r*wv.x + bv.x;
    o4.y = d1*r*wv.y + bv.y;
    o4.z = d2*r*wv.z + bv.z;
    o4.w = d3*r*wv.w + bv.w;
    ((float4*)(g_norm + (size_t)row*CDIM))[lane] = o4;
}

// ---------------------------------------------------------------------------
// SGEMM: g_pre[36864,640] = g_norm[36864,128] @ g_Wc[128,640]
// 64x64 tile, BK=64, 256 threads, 4x4 microtile
// ---------------------------------------------------------------------------
__global__ __launch_bounds__(256) void k_gemm() {
    __shared__ float As[64][64];   // [k][m] (transposed)
    __shared__ float Bs[64][64];   // [k][n]
    int tid = threadIdx.x;
    int tx = tid & 15, ty = tid >> 4;
    int m0 = blockIdx.y * 64, n0 = blockIdx.x * 64;
    float acc[4][4] = {};
#pragma unroll
    for (int kt = 0; kt < 2; kt++) {
        int k0 = kt * 64;
#pragma unroll
        for (int it = 0; it < 4; it++) {
            int slot = tid + it * 256;            // 1024 float4 slots
            int r = slot >> 4, kv = (slot & 15) << 2;
            float4 a = *(const float4*)(g_norm + (size_t)(m0 + r)*CDIM + k0 + kv);
            As[kv+0][r] = a.x; As[kv+1][r] = a.y; As[kv+2][r] = a.z; As[kv+3][r] = a.w;
        }
#pragma unroll
        for (int it = 0; it < 4; it++) {
            int slot = tid + it * 256;
            int kk = slot >> 4, nv = (slot & 15) << 2;
            *(float4*)&Bs[kk][nv] = *(const float4*)(g_Wc + (size_t)(k0 + kk)*PRE_N + n0 + nv);
        }
        __syncthreads();
#pragma unroll 8
        for (int k = 0; k < 64; k++) {
            float4 a4 = *(const float4*)&As[k][ty << 2];
            float4 b4 = *(const float4*)&Bs[k][tx << 2];
            float av[4] = {a4.x, a4.y, a4.z, a4.w};
            float bv[4] = {b4.x, b4.y, b4.z, b4.w};
#pragma unroll
            for (int i = 0; i < 4; i++)
#pragma unroll
                for (int j = 0; j < 4; j++)
                    acc[i][j] += av[i] * bv[j];
        }
        __syncthreads();
    }
#pragma unroll
    for (int i = 0; i < 4; i++) {
        float4 o = make_float4(acc[i][0], acc[i][1], acc[i][2], acc[i][3]);
        *(float4*)(g_pre + (size_t)(m0 + (ty<<2) + i)*PRE_N + n0 + (tx<<2)) = o;
    }
}

// ---------------------------------------------------------------------------
// Edge MLP tail + EML gate + gated message aggregation. One warp per token.
// lane owns hidden/channel indices h = lane + 32*i, i in 0..3
// ---------------------------------------------------------------------------
__global__ __launch_bounds__(256) void k_edge(
        const float* __restrict__ dw2, const float* __restrict__ db2,
        const float* __restrict__ rw2, const float* __restrict__ rb2,
        const float* __restrict__ vb,
        const float* __restrict__ gma, const float* __restrict__ lamp,
        const float* __restrict__ biasp) {
    int warp = threadIdx.x >> 5, lane = threadIdx.x & 31;
    int t = blockIdx.x * 8 + warp;
    int b_i = t / HW;
    int rem = t - b_i * HW;
    int y = rem / WDIM;
    int x = rem - y * WDIM;

    const float* prow = g_pre + (size_t)t * PRE_N;
    float Ad[4], Ar[4], w2d[4], w2r[4], vb4[4], msg[4] = {0.f, 0.f, 0.f, 0.f};
#pragma unroll
    for (int i = 0; i < 4; i++) {
        int h = lane + 32*i;
        Ad[i]  = prow[h];
        Ar[i]  = prow[256 + h];
        w2d[i] = dw2[h];
        w2r[i] = rw2[h];
        vb4[i] = vb[h];
    }
    float gamma = sp_f(gma[0]);
    float lam = lamp[0], ebias = biasp[0];
    float db2v = db2[0], rb2v = rb2[0];
    float mass = 0.f;

#pragma unroll
    for (int nb = 0; nb < 9; nb++) {
        int dy = nb / 3 - 1, dx = nb % 3 - 1;
        int yy = y + dy, xx = x + dx;
        bool ok = (unsigned)yy < (unsigned)HDIM && (unsigned)xx < (unsigned)WDIM;
        int ycl = ok ? yy : 0, xcl = ok ? xx : 0;
        const float* qrow = g_pre + (size_t)(((b_i * HDIM) + ycl) * WDIM + xcl) * PRE_N;
        float sd = 0.f, sr = 0.f;
        float V4[4];
#pragma unroll
        for (int i = 0; i < 4; i++) {
            int h = lane + 32*i;
            float bd = ok ? qrow[128 + h] : 0.f;
            float br = ok ? qrow[384 + h] : 0.f;
            V4[i]    = ok ? qrow[512 + h] : 0.f;
            float hd = Ad[i] + bd + g_rpb[nb*HID + h];
            float hr = Ar[i] + br + g_rpb[(NBH + nb)*HID + h];
            sd += gelu_f(hd) * w2d[i];
            sr += gelu_f(hr) * w2r[i];
        }
#pragma unroll
        for (int o = 16; o; o >>= 1) {
            sd += __shfl_xor_sync(0xffffffffu, sd, o);
            sr += __shfl_xor_sync(0xffffffffu, sr, o);
        }
        float drive = sd + db2v, res = sr + rb2v;
        float conduct = drive / (sp_f(res) + gamma + 1e-6f);
        float e = fminf(fmaxf(lam * conduct, -3.f), 3.f) + ebias;
        float gate = 1.f / (1.f + expf(-e));
#pragma unroll
        for (int i = 0; i < 4; i++) msg[i] += gate * (V4[i] + vb4[i]);
        mass += gate;
    }
    float inv = 1.f / fmaxf(mass, 1e-6f);
#pragma unroll
    for (int i = 0; i < 4; i++)
        g_msg[(size_t)t*CDIM + lane + 32*i] = msg[i] * inv;
}

// ---------------------------------------------------------------------------
// Output projection + residual + LayerNorm 2. One block (128 threads) / token.
// ---------------------------------------------------------------------------
__global__ __launch_bounds__(128) void k_out(
        const float* __restrict__ tokens,
        const float* __restrict__ ow, const float* __restrict__ ob,
        const float* __restrict__ lnw, const float* __restrict__ lnb,
        float* __restrict__ out) {
    __shared__ float ms[128];
    __shared__ float red[4];
    int t = blockIdx.x, c = threadIdx.x;
    ms[c] = g_msg[(size_t)t*CDIM + c];
    __syncthreads();
    float acc = ob[c];
#pragma unroll 8
    for (int k = 0; k < 128; k++)
        acc += ms[k] * ow[k*CDIM + c];
    float xr = tokens[(size_t)t*CDIM + c] + acc;

    float s = xr;
#pragma unroll
    for (int o = 16; o; o >>= 1) s += __shfl_xor_sync(0xffffffffu, s, o);
    if ((c & 31) == 0) red[c >> 5] = s;
    __syncthreads();
    float mean = (red[0] + red[1] + red[2] + red[3]) * (1.f/128.f);
    float d = xr - mean;
    __syncthreads();
    float v = d * d;
#pragma unroll
    for (int o = 16; o; o >>= 1) v += __shfl_xor_sync(0xffffffffu, v, o);
    if ((c & 31) == 0) red[c >> 5] = v;
    __syncthreads();
    float var = (red[0] + red[1] + red[2] + red[3]) * (1.f/128.f);
    out[(size_t)t*CDIM + c] = d * rsqrtf(var + 1e-5f) * lnw[c] + lnb[c];
}

// ---------------------------------------------------------------------------
extern "C" void kernel_launch(void* const* d_in, const int* in_sizes, int n_in,
                              void* d_out, int out_size) {
    const float* tokens = (const float*)d_in[0];
    const float* ln1w   = (const float*)d_in[1];
    const float* ln1b   = (const float*)d_in[2];
    const float* ln2w   = (const float*)d_in[3];
    const float* ln2b   = (const float*)d_in[4];
    const float* relp   = (const float*)d_in[5];
    const float* dw1    = (const float*)d_in[6];
    const float* db1    = (const float*)d_in[7];
    const float* dw2    = (const float*)d_in[8];
    const float* db2    = (const float*)d_in[9];
    const float* rw1    = (const float*)d_in[10];
    const float* rb1    = (const float*)d_in[11];
    const float* rw2    = (const float*)d_in[12];
    const float* rb2    = (const float*)d_in[13];
    const float* vw     = (const float*)d_in[14];
    const float* vb     = (const float*)d_in[15];
    const float* ow     = (const float*)d_in[16];
    const float* ob     = (const float*)d_in[17];
    const float* gma    = (const float*)d_in[18];
    const float* lam    = (const float*)d_in[19];
    const float* ebias  = (const float*)d_in[20];
    float* out = (float*)d_out;

    k_prep_w<<<(CDIM*PRE_N + 255)/256, 256>>>(dw1, rw1, vw);
    k_prep_rpb<<<(2*NBH*HID + 255)/256, 256>>>(relp, dw1, db1, rw1, rb1);
    k_ln1<<<NT/8, 256>>>(tokens, ln1w, ln1b);
    dim3 gg(PRE_N/64, NT/64);
    k_gemm<<<gg, 256>>>();
    k_edge<<<NT/8, 256>>>(dw2, db2, rw2, rb2, vb, gma, lam, ebias);
    k_out<<<NT, 128>>>(tokens, ow, ob, ln2w, ln2b, out);
}

// round 5
// speedup vs baseline: 1.5679x; 1.5679x over previous
#include <cuda_runtime.h>
#include <cuda_bf16.h>
#include <math.h>
#include <cstdint>

// Problem dims
#define BSZ 4
#define HDIM 96
#define WDIM 96
#define CDIM 128
#define HW (HDIM*WDIM)
#define NT (BSZ*HW)          // 36864 tokens
#define NBH 9
#define RPD 8
#define HID 128
#define PRE_N 640            // [Ad | Bd | Ar | Br | V] each 128 wide

// Scratch (no allocation allowed -> __device__ globals)
__device__ __nv_bfloat16 g_normh[(size_t)NT*CDIM];     // LN1 output, bf16
__device__ __nv_bfloat16 g_Wh[(size_t)PRE_N*CDIM];     // combined weights, [n][k] bf16
__device__ float g_pre[(size_t)NT*PRE_N];
__device__ float g_msg[(size_t)NT*CDIM];
__device__ float g_rpb[2*NBH*HID];                     // rel-pos + bias table, d then r

__device__ __forceinline__ float sp_f(float x) {
    return fmaxf(x, 0.f) + log1pf(expf(-fabsf(x)));
}
__device__ __forceinline__ float gelu_f(float x) {
    return 0.5f * x * (1.f + erff(x * 0.70710678118654752f));
}
__device__ __forceinline__ uint32_t smem_u32(const void* p) {
    uint32_t a;
    asm("{ .reg .u64 t; cvta.to.shared.u64 t, %1; cvt.u32.u64 %0, t; }" : "=r"(a) : "l"(p));
    return a;
}

// ---------------------------------------------------------------------------
// Weight prep: g_Wh[n][k] (transposed, bf16) for n-blocks {Ad, Bd, Ar, Br, V}
// Ad = W1a + W1c ; Bd = W1b - W1c (same for r); V = v_w
// ---------------------------------------------------------------------------
__global__ void k_prep_w(const float* __restrict__ dw1,
                         const float* __restrict__ rw1,
                         const float* __restrict__ vw) {
    int i = blockIdx.x * blockDim.x + threadIdx.x;
    if (i >= CDIM * PRE_N) return;
    int k = i / PRE_N, n = i % PRE_N;
    float v;
    if (n < 128)        v = dw1[k*HID + n]         + dw1[(256+k)*HID + n];
    else if (n < 256)   v = dw1[(128+k)*HID + (n-128)] - dw1[(256+k)*HID + (n-128)];
    else if (n < 384)   v = rw1[k*HID + (n-256)]       + rw1[(256+k)*HID + (n-256)];
    else if (n < 512)   v = rw1[(128+k)*HID + (n-384)] - rw1[(256+k)*HID + (n-384)];
    else                v = vw[k*CDIM + (n-512)];
    g_Wh[(size_t)n*CDIM + k] = __float2bfloat16(v);
}

// rpb[m][nb][j] = b1[j] + sum_p rel_pos[nb][p] * w1[384+p][j]
__global__ void k_prep_rpb(const float* __restrict__ relp,
                           const float* __restrict__ dw1, const float* __restrict__ db1,
                           const float* __restrict__ rw1, const float* __restrict__ rb1) {
    int i = blockIdx.x * blockDim.x + threadIdx.x;
    if (i >= 2 * NBH * HID) return;
    int m = i / (NBH*HID);
    int nb = (i / HID) % NBH;
    int j = i % HID;
    const float* w1 = m ? rw1 : dw1;
    const float* b1 = m ? rb1 : db1;
    float acc = b1[j];
#pragma unroll
    for (int p = 0; p < RPD; p++)
        acc += relp[nb*RPD + p] * w1[(384+p)*HID + j];
    g_rpb[i] = acc;
}

// ---------------------------------------------------------------------------
// LayerNorm 1: one warp per token row of 128, writes bf16
// ---------------------------------------------------------------------------
__global__ void k_ln1(const float* __restrict__ tokens,
                      const float* __restrict__ w, const float* __restrict__ b) {
    int warp = threadIdx.x >> 5, lane = threadIdx.x & 31;
    int row = blockIdx.x * 8 + warp;
    const float4 x = ((const float4*)(tokens + (size_t)row*CDIM))[lane];
    float s = x.x + x.y + x.z + x.w;
#pragma unroll
    for (int o = 16; o; o >>= 1) s += __shfl_xor_sync(0xffffffffu, s, o);
    float m = s * (1.f/128.f);
    float d0 = x.x - m, d1 = x.y - m, d2 = x.z - m, d3 = x.w - m;
    float v = d0*d0 + d1*d1 + d2*d2 + d3*d3;
#pragma unroll
    for (int o = 16; o; o >>= 1) v += __shfl_xor_sync(0xffffffffu, v, o);
    float r = rsqrtf(v * (1.f/128.f) + 1e-5f);
    const float4 wv = ((const float4*)w)[lane];
    const float4 bv = ((const float4*)b)[lane];
    __nv_bfloat162 o0 = __floats2bfloat162_rn(d0*r*wv.x + bv.x, d1*r*wv.y + bv.y);
    __nv_bfloat162 o1 = __floats2bfloat162_rn(d2*r*wv.z + bv.z, d3*r*wv.w + bv.w);
    __nv_bfloat162* orow = (__nv_bfloat162*)(g_normh + (size_t)row*CDIM);
    orow[lane*2 + 0] = o0;
    orow[lane*2 + 1] = o1;
}

// ---------------------------------------------------------------------------
// bf16 HMMA GEMM via mma.sync.m16n8k16 (portable sm_80+ path; tcgen05 is
// unavailable: the harness compiles PTX for plain compute_103).
// g_pre[36864,640] = norm[36864,128] @ Wc[128,640]
// CTA 128x128, BK=64 x2. 8 warps (2Mx4N), warp tile 64x32 = 4x4 atoms.
// Smem rows padded to 72 bf16 (144B: 144%128=16 -> conflict-free ldmatrix).
// ---------------------------------------------------------------------------
__global__ __launch_bounds__(256) void k_gemm_mma() {
    __shared__ __nv_bfloat16 As[128][72];
    __shared__ __nv_bfloat16 Bs[128][72];
    const int tid = threadIdx.x;
    const int wid = tid >> 5, lane = tid & 31;
    const int wm = wid & 1, wn = wid >> 1;           // 2 x 4 warp grid
    const int m0 = blockIdx.y * 128, n0 = blockIdx.x * 128;
    const int grp = lane >> 2, qid = lane & 3;

    float acc[4][4][4];
#pragma unroll
    for (int i = 0; i < 4; i++)
#pragma unroll
        for (int j = 0; j < 4; j++)
#pragma unroll
            for (int r = 0; r < 4; r++) acc[i][j][r] = 0.f;

    // precompute ldmatrix smem addresses (row part varies with k-step only by col)
    const int a_row = wm*64 + (lane & 15);
    const int a_colbase = (lane >> 4) << 3;
    const int b_row = wn*32 + ((lane >> 4) << 3) + (lane & 7);
    const int b_colbase = ((lane >> 3) & 1) << 3;

#pragma unroll
    for (int kc = 0; kc < 2; kc++) {
        const int k0g = kc * 64;
        // cooperative load: 128 rows x 64 cols for A and B (1024 float4 each)
#pragma unroll
        for (int it = 0; it < 4; it++) {
            int seg = tid + it * 256;
            int row = seg >> 3, c8 = (seg & 7) * 8;
            *(float4*)&As[row][c8] = *(const float4*)(g_normh + (size_t)(m0 + row)*CDIM + k0g + c8);
            *(float4*)&Bs[row][c8] = *(const float4*)(g_Wh   + (size_t)(n0 + row)*CDIM + k0g + c8);
        }
        __syncthreads();

#pragma unroll
        for (int ks = 0; ks < 4; ks++) {
            const int k0 = ks * 16;
            uint32_t afr[4][4], bfr[4][2];
#pragma unroll
            for (int mi = 0; mi < 4; mi++) {
                uint32_t addr = smem_u32(&As[a_row + mi*16][k0 + a_colbase]);
                asm volatile(
                    "ldmatrix.sync.aligned.m8n8.x4.shared.b16 {%0,%1,%2,%3}, [%4];"
                    : "=r"(afr[mi][0]), "=r"(afr[mi][1]), "=r"(afr[mi][2]), "=r"(afr[mi][3])
                    : "r"(addr));
            }
#pragma unroll
            for (int nj = 0; nj < 2; nj++) {
                uint32_t addr = smem_u32(&Bs[b_row + nj*16][k0 + b_colbase]);
                asm volatile(
                    "ldmatrix.sync.aligned.m8n8.x4.shared.b16 {%0,%1,%2,%3}, [%4];"
                    : "=r"(bfr[2*nj][0]), "=r"(bfr[2*nj][1]),
                      "=r"(bfr[2*nj+1][0]), "=r"(bfr[2*nj+1][1])
                    : "r"(addr));
            }
#pragma unroll
            for (int mi = 0; mi < 4; mi++)
#pragma unroll
                for (int ni = 0; ni < 4; ni++)
                    asm volatile(
                        "mma.sync.aligned.m16n8k16.row.col.f32.bf16.bf16.f32 "
                        "{%0,%1,%2,%3}, {%4,%5,%6,%7}, {%8,%9}, {%0,%1,%2,%3};"
                        : "+f"(acc[mi][ni][0]), "+f"(acc[mi][ni][1]),
                          "+f"(acc[mi][ni][2]), "+f"(acc[mi][ni][3])
                        : "r"(afr[mi][0]), "r"(afr[mi][1]), "r"(afr[mi][2]), "r"(afr[mi][3]),
                          "r"(bfr[ni][0]), "r"(bfr[ni][1]));
        }
        __syncthreads();
    }

    // epilogue: fp32 fragments straight to g_pre
#pragma unroll
    for (int mi = 0; mi < 4; mi++) {
        int r0 = m0 + wm*64 + mi*16 + grp;
#pragma unroll
        for (int ni = 0; ni < 4; ni++) {
            int c = n0 + wn*32 + ni*8 + qid*2;
            *(float2*)(g_pre + (size_t)r0*PRE_N + c)     = make_float2(acc[mi][ni][0], acc[mi][ni][1]);
            *(float2*)(g_pre + (size_t)(r0+8)*PRE_N + c) = make_float2(acc[mi][ni][2], acc[mi][ni][3]);
        }
    }
}

// ---------------------------------------------------------------------------
// Edge MLP tail + EML gate + gated message aggregation. One warp per token.
// ---------------------------------------------------------------------------
__global__ __launch_bounds__(256) void k_edge(
        const float* __restrict__ dw2, const float* __restrict__ db2,
        const float* __restrict__ rw2, const float* __restrict__ rb2,
        const float* __restrict__ vb,
        const float* __restrict__ gma, const float* __restrict__ lamp,
        const float* __restrict__ biasp) {
    int warp = threadIdx.x >> 5, lane = threadIdx.x & 31;
    int t = blockIdx.x * 8 + warp;
    int b_i = t / HW;
    int rem = t - b_i * HW;
    int y = rem / WDIM;
    int x = rem - y * WDIM;

    const float* prow = g_pre + (size_t)t * PRE_N;
    float Ad[4], Ar[4], w2d[4], w2r[4], vb4[4], msg[4] = {0.f, 0.f, 0.f, 0.f};
#pragma unroll
    for (int i = 0; i < 4; i++) {
        int h = lane + 32*i;
        Ad[i]  = prow[h];
        Ar[i]  = prow[256 + h];
        w2d[i] = dw2[h];
        w2r[i] = rw2[h];
        vb4[i] = vb[h];
    }
    float gamma = sp_f(gma[0]);
    float lam = lamp[0], ebias = biasp[0];
    float db2v = db2[0], rb2v = rb2[0];
    float mass = 0.f;

#pragma unroll
    for (int nb = 0; nb < 9; nb++) {
        int dy = nb / 3 - 1, dx = nb % 3 - 1;
        int yy = y + dy, xx = x + dx;
        bool ok = (unsigned)yy < (unsigned)HDIM && (unsigned)xx < (unsigned)WDIM;
        int ycl = ok ? yy : 0, xcl = ok ? xx : 0;
        const float* qrow = g_pre + (size_t)(((b_i * HDIM) + ycl) * WDIM + xcl) * PRE_N;
        float sd = 0.f, sr = 0.f;
        float V4[4];
#pragma unroll
        for (int i = 0; i < 4; i++) {
            int h = lane + 32*i;
            float bd = ok ? qrow[128 + h] : 0.f;
            float br = ok ? qrow[384 + h] : 0.f;
            V4[i]    = ok ? qrow[512 + h] : 0.f;
            float hd = Ad[i] + bd + g_rpb[nb*HID + h];
            float hr = Ar[i] + br + g_rpb[(NBH + nb)*HID + h];
            sd += gelu_f(hd) * w2d[i];
            sr += gelu_f(hr) * w2r[i];
        }
#pragma unroll
        for (int o = 16; o; o >>= 1) {
            sd += __shfl_xor_sync(0xffffffffu, sd, o);
            sr += __shfl_xor_sync(0xffffffffu, sr, o);
        }
        float drive = sd + db2v, res = sr + rb2v;
        float conduct = drive / (sp_f(res) + gamma + 1e-6f);
        float e = fminf(fmaxf(lam * conduct, -3.f), 3.f) + ebias;
        float gate = 1.f / (1.f + expf(-e));
#pragma unroll
        for (int i = 0; i < 4; i++) msg[i] += gate * (V4[i] + vb4[i]);
        mass += gate;
    }
    float inv = 1.f / fmaxf(mass, 1e-6f);
#pragma unroll
    for (int i = 0; i < 4; i++)
        g_msg[(size_t)t*CDIM + lane + 32*i] = msg[i] * inv;
}

// ---------------------------------------------------------------------------
// Output projection + residual + LayerNorm 2. One block (128 threads) / token.
// ---------------------------------------------------------------------------
__global__ __launch_bounds__(128) void k_out(
        const float* __restrict__ tokens,
        const float* __restrict__ ow, const float* __restrict__ ob,
        const float* __restrict__ lnw, const float* __restrict__ lnb,
        float* __restrict__ out) {
    __shared__ float ms[128];
    __shared__ float red[4];
    int t = blockIdx.x, c = threadIdx.x;
    ms[c] = g_msg[(size_t)t*CDIM + c];
    __syncthreads();
    float acc = ob[c];
#pragma unroll 8
    for (int k = 0; k < 128; k++)
        acc += ms[k] * ow[k*CDIM + c];
    float xr = tokens[(size_t)t*CDIM + c] + acc;

    float s = xr;
#pragma unroll
    for (int o = 16; o; o >>= 1) s += __shfl_xor_sync(0xffffffffu, s, o);
    if ((c & 31) == 0) red[c >> 5] = s;
    __syncthreads();
    float mean = (red[0] + red[1] + red[2] + red[3]) * (1.f/128.f);
    float d = xr - mean;
    __syncthreads();
    float v = d * d;
#pragma unroll
    for (int o = 16; o; o >>= 1) v += __shfl_xor_sync(0xffffffffu, v, o);
    if ((c & 31) == 0) red[c >> 5] = v;
    __syncthreads();
    float var = (red[0] + red[1] + red[2] + red[3]) * (1.f/128.f);
    out[(size_t)t*CDIM + c] = d * rsqrtf(var + 1e-5f) * lnw[c] + lnb[c];
}

// ---------------------------------------------------------------------------
extern "C" void kernel_launch(void* const* d_in, const int* in_sizes, int n_in,
                              void* d_out, int out_size) {
    const float* tokens = (const float*)d_in[0];
    const float* ln1w   = (const float*)d_in[1];
    const float* ln1b   = (const float*)d_in[2];
    const float* ln2w   = (const float*)d_in[3];
    const float* ln2b   = (const float*)d_in[4];
    const float* relp   = (const float*)d_in[5];
    const float* dw1    = (const float*)d_in[6];
    const float* db1    = (const float*)d_in[7];
    const float* dw2    = (const float*)d_in[8];
    const float* db2    = (const float*)d_in[9];
    const float* rw1    = (const float*)d_in[10];
    const float* rb1    = (const float*)d_in[11];
    const float* rw2    = (const float*)d_in[12];
    const float* rb2    = (const float*)d_in[13];
    const float* vw     = (const float*)d_in[14];
    const float* vb     = (const float*)d_in[15];
    const float* ow     = (const float*)d_in[16];
    const float* ob     = (const float*)d_in[17];
    const float* gma    = (const float*)d_in[18];
    const float* lam    = (const float*)d_in[19];
    const float* ebias  = (const float*)d_in[20];
    float* out = (float*)d_out;

    k_prep_w<<<(CDIM*PRE_N + 255)/256, 256>>>(dw1, rw1, vw);
    k_prep_rpb<<<(2*NBH*HID + 255)/256, 256>>>(relp, dw1, db1, rw1, rb1);
    k_ln1<<<NT/8, 256>>>(tokens, ln1w, ln1b);
    dim3 gg(PRE_N/128, NT/128);
    k_gemm_mma<<<gg, 256>>>();
    k_edge<<<NT/8, 256>>>(dw2, db2, rw2, rb2, vb, gma, lam, ebias);
    k_out<<<NT, 128>>>(tokens, ow, ob, ln2w, ln2b, out);
}

// round 17
// speedup vs baseline: 2.4342x; 1.5525x over previous
#include <cuda_runtime.h>
#include <cuda_bf16.h>
#include <math.h>
#include <cstdint>

// Problem dims
#define BSZ 4
#define HDIM 96
#define WDIM 96
#define CDIM 128
#define HW (HDIM*WDIM)
#define NT (BSZ*HW)          // 36864 tokens
#define NBH 9
#define RPD 8
#define HID 128
#define PRE_N 640            // [Ad | Bd | Ar | Br | V] each 128 wide

// Scratch (no allocation allowed -> __device__ globals)
__device__ __nv_bfloat16 g_normh[(size_t)NT*CDIM];     // LN1 output, bf16
__device__ __nv_bfloat16 g_Wh[(size_t)PRE_N*CDIM];     // combined weights, [n][k] bf16
__device__ __nv_bfloat16 g_Oh[(size_t)CDIM*CDIM];      // o_w transposed, [n][k] bf16
__device__ float g_pre[(size_t)NT*PRE_N];
__device__ __nv_bfloat16 g_msgh[(size_t)NT*CDIM];      // message, bf16
__device__ float g_rpb[2*NBH*HID];                     // rel-pos + bias table, d then r

__device__ __forceinline__ float sp_f(float x) {
    return fmaxf(x, 0.f) + log1pf(expf(-fabsf(x)));
}
__device__ __forceinline__ float gelu_f(float x) {
    return 0.5f * x * (1.f + erff(x * 0.70710678118654752f));
}
__device__ __forceinline__ uint32_t smem_u32(const void* p) {
    uint32_t a;
    asm("{ .reg .u64 t; cvta.to.shared.u64 t, %1; cvt.u32.u64 %0, t; }" : "=r"(a) : "l"(p));
    return a;
}

// ---------------------------------------------------------------------------
// Weight prep: g_Wh[n][k] bf16 for n-blocks {Ad, Bd, Ar, Br, V}; g_Oh[n][k]=o_w^T
// ---------------------------------------------------------------------------
__global__ void k_prep_w(const float* __restrict__ dw1,
                         const float* __restrict__ rw1,
                         const float* __restrict__ vw,
                         const float* __restrict__ ow) {
    int i = blockIdx.x * blockDim.x + threadIdx.x;
    if (i >= CDIM * (PRE_N + CDIM)) return;
    int k = i / (PRE_N + CDIM), n = i % (PRE_N + CDIM);
    if (n >= PRE_N) {
        int nn = n - PRE_N;
        g_Oh[(size_t)nn*CDIM + k] = __float2bfloat16(ow[k*CDIM + nn]);
        return;
    }
    float v;
    if (n < 128)        v = dw1[k*HID + n]         + dw1[(256+k)*HID + n];
    else if (n < 256)   v = dw1[(128+k)*HID + (n-128)] - dw1[(256+k)*HID + (n-128)];
    else if (n < 384)   v = rw1[k*HID + (n-256)]       + rw1[(256+k)*HID + (n-256)];
    else if (n < 512)   v = rw1[(128+k)*HID + (n-384)] - rw1[(256+k)*HID + (n-384)];
    else                v = vw[k*CDIM + (n-512)];
    g_Wh[(size_t)n*CDIM + k] = __float2bfloat16(v);
}

// rpb[m][nb][j] = b1[j] + sum_p rel_pos[nb][p] * w1[384+p][j]
__global__ void k_prep_rpb(const float* __restrict__ relp,
                           const float* __restrict__ dw1, const float* __restrict__ db1,
                           const float* __restrict__ rw1, const float* __restrict__ rb1) {
    int i = blockIdx.x * blockDim.x + threadIdx.x;
    if (i >= 2 * NBH * HID) return;
    int m = i / (NBH*HID);
    int nb = (i / HID) % NBH;
    int j = i % HID;
    const float* w1 = m ? rw1 : dw1;
    const float* b1 = m ? rb1 : db1;
    float acc = b1[j];
#pragma unroll
    for (int p = 0; p < RPD; p++)
        acc += relp[nb*RPD + p] * w1[(384+p)*HID + j];
    g_rpb[i] = acc;
}

// ---------------------------------------------------------------------------
// LayerNorm 1: one warp per token row of 128, writes bf16
// ---------------------------------------------------------------------------
__global__ void k_ln1(const float* __restrict__ tokens,
                      const float* __restrict__ w, const float* __restrict__ b) {
    int warp = threadIdx.x >> 5, lane = threadIdx.x & 31;
    int row = blockIdx.x * 8 + warp;
    const float4 x = ((const float4*)(tokens + (size_t)row*CDIM))[lane];
    float s = x.x + x.y + x.z + x.w;
#pragma unroll
    for (int o = 16; o; o >>= 1) s += __shfl_xor_sync(0xffffffffu, s, o);
    float m = s * (1.f/128.f);
    float d0 = x.x - m, d1 = x.y - m, d2 = x.z - m, d3 = x.w - m;
    float v = d0*d0 + d1*d1 + d2*d2 + d3*d3;
#pragma unroll
    for (int o = 16; o; o >>= 1) v += __shfl_xor_sync(0xffffffffu, v, o);
    float r = rsqrtf(v * (1.f/128.f) + 1e-5f);
    const float4 wv = ((const float4*)w)[lane];
    const float4 bv = ((const float4*)b)[lane];
    __nv_bfloat162 o0 = __floats2bfloat162_rn(d0*r*wv.x + bv.x, d1*r*wv.y + bv.y);
    __nv_bfloat162 o1 = __floats2bfloat162_rn(d2*r*wv.z + bv.z, d3*r*wv.w + bv.w);
    __nv_bfloat162* orow = (__nv_bfloat162*)(g_normh + (size_t)row*CDIM);
    orow[lane*2 + 0] = o0;
    orow[lane*2 + 1] = o1;
}

// ---------------------------------------------------------------------------
// bf16 HMMA GEMM: g_pre[36864,640] = norm @ Wc. CTA 128x128, 8 warps 2Mx4N.
// ---------------------------------------------------------------------------
__global__ __launch_bounds__(256) void k_gemm_mma() {
    __shared__ __nv_bfloat16 As[128][72];
    __shared__ __nv_bfloat16 Bs[128][72];
    const int tid = threadIdx.x;
    const int wid = tid >> 5, lane = tid & 31;
    const int wm = wid & 1, wn = wid >> 1;
    const int m0 = blockIdx.y * 128, n0 = blockIdx.x * 128;
    const int grp = lane >> 2, qid = lane & 3;

    float acc[4][4][4];
#pragma unroll
    for (int i = 0; i < 4; i++)
#pragma unroll
        for (int j = 0; j < 4; j++)
#pragma unroll
            for (int r = 0; r < 4; r++) acc[i][j][r] = 0.f;

    const int a_row = wm*64 + (lane & 15);
    const int a_colbase = (lane >> 4) << 3;
    const int b_row = wn*32 + ((lane >> 4) << 3) + (lane & 7);
    const int b_colbase = ((lane >> 3) & 1) << 3;

#pragma unroll
    for (int kc = 0; kc < 2; kc++) {
        const int k0g = kc * 64;
#pragma unroll
        for (int it = 0; it < 4; it++) {
            int seg = tid + it * 256;
            int row = seg >> 3, c8 = (seg & 7) * 8;
            *(float4*)&As[row][c8] = *(const float4*)(g_normh + (size_t)(m0 + row)*CDIM + k0g + c8);
            *(float4*)&Bs[row][c8] = *(const float4*)(g_Wh   + (size_t)(n0 + row)*CDIM + k0g + c8);
        }
        __syncthreads();

#pragma unroll
        for (int ks = 0; ks < 4; ks++) {
            const int k0 = ks * 16;
            uint32_t afr[4][4], bfr[4][2];
#pragma unroll
            for (int mi = 0; mi < 4; mi++) {
                uint32_t addr = smem_u32(&As[a_row + mi*16][k0 + a_colbase]);
                asm volatile(
                    "ldmatrix.sync.aligned.m8n8.x4.shared.b16 {%0,%1,%2,%3}, [%4];"
                    : "=r"(afr[mi][0]), "=r"(afr[mi][1]), "=r"(afr[mi][2]), "=r"(afr[mi][3])
                    : "r"(addr));
            }
#pragma unroll
            for (int nj = 0; nj < 2; nj++) {
                uint32_t addr = smem_u32(&Bs[b_row + nj*16][k0 + b_colbase]);
                asm volatile(
                    "ldmatrix.sync.aligned.m8n8.x4.shared.b16 {%0,%1,%2,%3}, [%4];"
                    : "=r"(bfr[2*nj][0]), "=r"(bfr[2*nj][1]),
                      "=r"(bfr[2*nj+1][0]), "=r"(bfr[2*nj+1][1])
                    : "r"(addr));
            }
#pragma unroll
            for (int mi = 0; mi < 4; mi++)
#pragma unroll
                for (int ni = 0; ni < 4; ni++)
                    asm volatile(
                        "mma.sync.aligned.m16n8k16.row.col.f32.bf16.bf16.f32 "
                        "{%0,%1,%2,%3}, {%4,%5,%6,%7}, {%8,%9}, {%0,%1,%2,%3};"
                        : "+f"(acc[mi][ni][0]), "+f"(acc[mi][ni][1]),
                          "+f"(acc[mi][ni][2]), "+f"(acc[mi][ni][3])
                        : "r"(afr[mi][0]), "r"(afr[mi][1]), "r"(afr[mi][2]), "r"(afr[mi][3]),
                          "r"(bfr[ni][0]), "r"(bfr[ni][1]));
        }
        __syncthreads();
    }

#pragma unroll
    for (int mi = 0; mi < 4; mi++) {
        int r0 = m0 + wm*64 + mi*16 + grp;
#pragma unroll
        for (int ni = 0; ni < 4; ni++) {
            int c = n0 + wn*32 + ni*8 + qid*2;
            *(float2*)(g_pre + (size_t)r0*PRE_N + c)     = make_float2(acc[mi][ni][0], acc[mi][ni][1]);
            *(float2*)(g_pre + (size_t)(r0+8)*PRE_N + c) = make_float2(acc[mi][ni][2], acc[mi][ni][3]);
        }
    }
}

// ---------------------------------------------------------------------------
// Edge MLP tail + EML gate + gated message aggregation. One warp per token.
// Lane owns contiguous h = lane*4..lane*4+3 -> float4 loads. Output bf16.
// ---------------------------------------------------------------------------
__global__ __launch_bounds__(256) void k_edge(
        const float* __restrict__ dw2, const float* __restrict__ db2,
        const float* __restrict__ rw2, const float* __restrict__ rb2,
        const float* __restrict__ vb,
        const float* __restrict__ gma, const float* __restrict__ lamp,
        const float* __restrict__ biasp) {
    int warp = threadIdx.x >> 5, lane = threadIdx.x & 31;
    int t = blockIdx.x * 8 + warp;
    int b_i = t / HW;
    int rem = t - b_i * HW;
    int y = rem / WDIM;
    int x = rem - y * WDIM;
    const int hb = lane * 4;

    const float* prow = g_pre + (size_t)t * PRE_N;
    const float4 Ad   = *(const float4*)(prow + hb);
    const float4 Ar   = *(const float4*)(prow + 256 + hb);
    const float4 w2d4 = *(const float4*)(dw2 + hb);
    const float4 w2r4 = *(const float4*)(rw2 + hb);
    const float4 vb4  = *(const float4*)(vb + hb);
    float msg[4] = {0.f, 0.f, 0.f, 0.f};

    float gamma = sp_f(gma[0]);
    float lam = lamp[0], ebias = biasp[0];
    float db2v = db2[0], rb2v = rb2[0];
    float mass = 0.f;

#pragma unroll
    for (int nb = 0; nb < 9; nb++) {
        int dy = nb / 3 - 1, dx = nb % 3 - 1;
        int yy = y + dy, xx = x + dx;
        bool ok = (unsigned)yy < (unsigned)HDIM && (unsigned)xx < (unsigned)WDIM;
        int ycl = ok ? yy : 0, xcl = ok ? xx : 0;
        const float* qrow = g_pre + (size_t)(((b_i * HDIM) + ycl) * WDIM + xcl) * PRE_N;
        const float4 zero = make_float4(0.f, 0.f, 0.f, 0.f);
        float4 bd = ok ? *(const float4*)(qrow + 128 + hb) : zero;
        float4 br = ok ? *(const float4*)(qrow + 384 + hb) : zero;
        float4 V4 = ok ? *(const float4*)(qrow + 512 + hb) : zero;
        const float4 rpd = *(const float4*)(g_rpb + nb*HID + hb);
        const float4 rpr = *(const float4*)(g_rpb + (NBH + nb)*HID + hb);

        float sd = gelu_f(Ad.x + bd.x + rpd.x) * w2d4.x
                 + gelu_f(Ad.y + bd.y + rpd.y) * w2d4.y
                 + gelu_f(Ad.z + bd.z + rpd.z) * w2d4.z
                 + gelu_f(Ad.w + bd.w + rpd.w) * w2d4.w;
        float sr = gelu_f(Ar.x + br.x + rpr.x) * w2r4.x
                 + gelu_f(Ar.y + br.y + rpr.y) * w2r4.y
                 + gelu_f(Ar.z + br.z + rpr.z) * w2r4.z
                 + gelu_f(Ar.w + br.w + rpr.w) * w2r4.w;
#pragma unroll
        for (int o = 16; o; o >>= 1) {
            sd += __shfl_xor_sync(0xffffffffu, sd, o);
            sr += __shfl_xor_sync(0xffffffffu, sr, o);
        }
        float drive = sd + db2v, res = sr + rb2v;
        float conduct = drive / (sp_f(res) + gamma + 1e-6f);
        float e = fminf(fmaxf(lam * conduct, -3.f), 3.f) + ebias;
        float gate = 1.f / (1.f + expf(-e));
        msg[0] += gate * (V4.x + vb4.x);
        msg[1] += gate * (V4.y + vb4.y);
        msg[2] += gate * (V4.z + vb4.z);
        msg[3] += gate * (V4.w + vb4.w);
        mass += gate;
    }
    float inv = 1.f / fmaxf(mass, 1e-6f);
    __nv_bfloat162 p0 = __floats2bfloat162_rn(msg[0]*inv, msg[1]*inv);
    __nv_bfloat162 p1 = __floats2bfloat162_rn(msg[2]*inv, msg[3]*inv);
    uint2 pk;
    pk.x = *(uint32_t*)&p0;
    pk.y = *(uint32_t*)&p1;
    *(uint2*)(g_msgh + (size_t)t*CDIM + hb) = pk;
}

// ---------------------------------------------------------------------------
// Fused output projection (HMMA) + residual + LayerNorm 2.
// out[m0..m0+127][0..127] = LN(tokens + msg @ o_w + ob). 288 CTAs, 8 warps.
// Smem overlay union: A/B staging tiles need 2*128*72*2 = 36864B;
// the fp32 epilogue buffer needs 64*132*4 = 33792B. Size for the max.
// ---------------------------------------------------------------------------
#define OUT_SMEM_BYTES (2*128*72*2)   // 36864 > 64*132*4 = 33792
__global__ __launch_bounds__(256) void k_out_mma(
        const float* __restrict__ tokens,
        const float* __restrict__ ob,
        const float* __restrict__ lnw, const float* __restrict__ lnb,
        float* __restrict__ out) {
    __shared__ __align__(16) char sm[OUT_SMEM_BYTES];
    __nv_bfloat16 (*As)[72] = (__nv_bfloat16(*)[72])sm;                    // 18432B
    __nv_bfloat16 (*Bs)[72] = (__nv_bfloat16(*)[72])(sm + 128*72*2);       // +18432B
    float (*sbuf)[132] = (float(*)[132])sm;                                // 33792B overlay

    const int tid = threadIdx.x;
    const int wid = tid >> 5, lane = tid & 31;
    const int wm = wid & 1, wn = wid >> 1;
    const int m0 = blockIdx.x * 128;
    const int grp = lane >> 2, qid = lane & 3;

    float acc[4][4][4];
#pragma unroll
    for (int i = 0; i < 4; i++)
#pragma unroll
        for (int j = 0; j < 4; j++)
#pragma unroll
            for (int r = 0; r < 4; r++) acc[i][j][r] = 0.f;

    const int a_row = wm*64 + (lane & 15);
    const int a_colbase = (lane >> 4) << 3;
    const int b_row = wn*32 + ((lane >> 4) << 3) + (lane & 7);
    const int b_colbase = ((lane >> 3) & 1) << 3;

#pragma unroll
    for (int kc = 0; kc < 2; kc++) {
        const int k0g = kc * 64;
#pragma unroll
        for (int it = 0; it < 4; it++) {
            int seg = tid + it * 256;
            int row = seg >> 3, c8 = (seg & 7) * 8;
            *(float4*)&As[row][c8] = *(const float4*)(g_msgh + (size_t)(m0 + row)*CDIM + k0g + c8);
            *(float4*)&Bs[row][c8] = *(const float4*)(g_Oh   + (size_t)row*CDIM + k0g + c8);
        }
        __syncthreads();

#pragma unroll
        for (int ks = 0; ks < 4; ks++) {
            const int k0 = ks * 16;
            uint32_t afr[4][4], bfr[4][2];
#pragma unroll
            for (int mi = 0; mi < 4; mi++) {
                uint32_t addr = smem_u32(&As[a_row + mi*16][k0 + a_colbase]);
                asm volatile(
                    "ldmatrix.sync.aligned.m8n8.x4.shared.b16 {%0,%1,%2,%3}, [%4];"
                    : "=r"(afr[mi][0]), "=r"(afr[mi][1]), "=r"(afr[mi][2]), "=r"(afr[mi][3])
                    : "r"(addr));
            }
#pragma unroll
            for (int nj = 0; nj < 2; nj++) {
                uint32_t addr = smem_u32(&Bs[b_row + nj*16][k0 + b_colbase]);
                asm volatile(
                    "ldmatrix.sync.aligned.m8n8.x4.shared.b16 {%0,%1,%2,%3}, [%4];"
                    : "=r"(bfr[2*nj][0]), "=r"(bfr[2*nj][1]),
                      "=r"(bfr[2*nj+1][0]), "=r"(bfr[2*nj+1][1])
                    : "r"(addr));
            }
#pragma unroll
            for (int mi = 0; mi < 4; mi++)
#pragma unroll
                for (int ni = 0; ni < 4; ni++)
                    asm volatile(
                        "mma.sync.aligned.m16n8k16.row.col.f32.bf16.bf16.f32 "
                        "{%0,%1,%2,%3}, {%4,%5,%6,%7}, {%8,%9}, {%0,%1,%2,%3};"
                        : "+f"(acc[mi][ni][0]), "+f"(acc[mi][ni][1]),
                          "+f"(acc[mi][ni][2]), "+f"(acc[mi][ni][3])
                        : "r"(afr[mi][0]), "r"(afr[mi][1]), "r"(afr[mi][2]), "r"(afr[mi][3]),
                          "r"(bfr[ni][0]), "r"(bfr[ni][1]));
        }
        __syncthreads();
    }

    // Epilogue in two halves of 64 rows, staged through sbuf (pad 132: conflict-free)
#pragma unroll
    for (int half = 0; half < 2; half++) {
        if (wm == half) {
#pragma unroll
            for (int mi = 0; mi < 4; mi++) {
                int lr = mi*16 + grp;
#pragma unroll
                for (int ni = 0; ni < 4; ni++) {
                    int c = wn*32 + ni*8 + qid*2;
                    sbuf[lr][c]   = acc[mi][ni][0];
                    sbuf[lr][c+1] = acc[mi][ni][1];
                    sbuf[lr+8][c]   = acc[mi][ni][2];
                    sbuf[lr+8][c+1] = acc[mi][ni][3];
                }
            }
        }
        __syncthreads();
        const float4 o4 = ((const float4*)ob)[lane];
        const float4 w4 = ((const float4*)lnw)[lane];
        const float4 b4 = ((const float4*)lnb)[lane];
#pragma unroll
        for (int rr = 0; rr < 8; rr++) {
            int r = wid*8 + rr;
            int gr = m0 + half*64 + r;
            float4 a = *(float4*)&sbuf[r][lane*4];
            float4 tk = *(const float4*)(tokens + (size_t)gr*CDIM + lane*4);
            float x0 = tk.x + a.x + o4.x;
            float x1 = tk.y + a.y + o4.y;
            float x2 = tk.z + a.z + o4.z;
            float x3 = tk.w + a.w + o4.w;
            float s = x0 + x1 + x2 + x3;
#pragma unroll
            for (int o = 16; o; o >>= 1) s += __shfl_xor_sync(0xffffffffu, s, o);
            float mean = s * (1.f/128.f);
            float d0 = x0 - mean, d1 = x1 - mean, d2 = x2 - mean, d3 = x3 - mean;
            float v = d0*d0 + d1*d1 + d2*d2 + d3*d3;
#pragma unroll
            for (int o = 16; o; o >>= 1) v += __shfl_xor_sync(0xffffffffu, v, o);
            float rinv = rsqrtf(v * (1.f/128.f) + 1e-5f);
            float4 ov;
            ov.x = d0*rinv*w4.x + b4.x;
            ov.y = d1*rinv*w4.y + b4.y;
            ov.z = d2*rinv*w4.z + b4.z;
            ov.w = d3*rinv*w4.w + b4.w;
            *(float4*)(out + (size_t)gr*CDIM + lane*4) = ov;
        }
        __syncthreads();
    }
}

// ---------------------------------------------------------------------------
extern "C" void kernel_launch(void* const* d_in, const int* in_sizes, int n_in,
                              void* d_out, int out_size) {
    const float* tokens = (const float*)d_in[0];
    const float* ln1w   = (const float*)d_in[1];
    const float* ln1b   = (const float*)d_in[2];
    const float* ln2w   = (const float*)d_in[3];
    const float* ln2b   = (const float*)d_in[4];
    const float* relp   = (const float*)d_in[5];
    const float* dw1    = (const float*)d_in[6];
    const float* db1    = (const float*)d_in[7];
    const float* dw2    = (const float*)d_in[8];
    const float* db2    = (const float*)d_in[9];
    const float* rw1    = (const float*)d_in[10];
    const float* rb1    = (const float*)d_in[11];
    const float* rw2    = (const float*)d_in[12];
    const float* rb2    = (const float*)d_in[13];
    const float* vw     = (const float*)d_in[14];
    const float* vb     = (const float*)d_in[15];
    const float* ow     = (const float*)d_in[16];
    const float* ob     = (const float*)d_in[17];
    const float* gma    = (const float*)d_in[18];
    const float* lam    = (const float*)d_in[19];
    const float* ebias  = (const float*)d_in[20];
    float* out = (float*)d_out;

    k_prep_w<<<(CDIM*(PRE_N+CDIM) + 255)/256, 256>>>(dw1, rw1, vw, ow);
    k_prep_rpb<<<(2*NBH*HID + 255)/256, 256>>>(relp, dw1, db1, rw1, rb1);
    k_ln1<<<NT/8, 256>>>(tokens, ln1w, ln1b);
    dim3 gg(PRE_N/128, NT/128);
    k_gemm_mma<<<gg, 256>>>();
    k_edge<<<NT/8, 256>>>(dw2, db2, rw2, rb2, vb, gma, lam, ebias);
    k_out_mma<<<NT/128, 256>>>(tokens, ob, ln2w, ln2b, out);
}